// round 13
// baseline (speedup 1.0000x reference)
#include <cuda_runtime.h>
#include <cuda_bf16.h>
#include <cstdint>
#include <cstddef>

#define NROWS 131072
#define NSEQ 64
#define TSTEPS 2048

// ---------------- scratch ----------------
__device__ __align__(16) float g_WihHi[1024 * 256];
__device__ __align__(16) float g_WihLo[1024 * 256];
__device__ float g_bih[1024];
__device__ __align__(16) uint4 g_WpackH[128 * 256];
__device__ float g_Wp2T[512 * 32];
__device__ __align__(16) float g_WpeHi[512 * 256];
__device__ __align__(16) float g_WpeLo[512 * 256];
__device__ float g_bpe[512];
__device__ __align__(16) float g_WveHi[512 * 512];
__device__ __align__(16) float g_WveLo[512 * 512];
__device__ float g_bve[512];
__device__ __align__(16) float g_xg[(size_t)NROWS * 1024];   // xg; reused as HP/HV after LSTM
__device__ __align__(16) float g_hs[(size_t)NROWS * 256];
__device__ int g_fixctr;
__device__ int g_fixlist[65536];

// ---------------- helpers ----------------
__device__ __forceinline__ unsigned long long ffma2(unsigned long long a, unsigned long long b, unsigned long long c) {
    asm("fma.rn.f32x2 %0, %1, %2, %3;" : "=l"(c) : "l"(a), "l"(b), "l"(c));
    return c;
}
__device__ __forceinline__ void unpack2(unsigned long long v, float& a, float& b) {
    asm("mov.b64 {%0, %1}, %2;" : "=f"(a), "=f"(b) : "l"(v));
}
__device__ __forceinline__ unsigned long long pack2b(unsigned lo, unsigned hi) {
    unsigned long long r;
    asm("mov.b64 %0, {%1, %2};" : "=l"(r) : "r"(lo), "r"(hi));
    return r;
}
__device__ __forceinline__ unsigned long long bfexp(unsigned r) {
    return pack2b(r << 16, r & 0xffff0000u);
}
__device__ __forceinline__ float sigf(float x) { return __fdividef(1.f, 1.f + __expf(-x)); }
__device__ __forceinline__ float tanha(float x) {
    float y;
    asm("tanh.approx.f32 %0, %1;" : "=f"(y) : "f"(x));
    return y;
}
__device__ __forceinline__ void split_tf32(float x, uint32_t& h, uint32_t& l) {
    asm("cvt.rna.tf32.f32 %0, %1;" : "=r"(h) : "f"(x));
    float lo = x - __uint_as_float(h);
    asm("cvt.rna.tf32.f32 %0, %1;" : "=r"(l) : "f"(lo));
}
__device__ __forceinline__ uint32_t tf32r(float x) {
    uint32_t h;
    asm("cvt.rna.tf32.f32 %0, %1;" : "=r"(h) : "f"(x));
    return h;
}
__device__ __forceinline__ void mma_tf32(float* d, const uint32_t* a, const uint32_t* b) {
    asm volatile(
        "mma.sync.aligned.m16n8k8.row.col.f32.tf32.tf32.f32 "
        "{%0,%1,%2,%3}, {%4,%5,%6,%7}, {%8,%9}, {%0,%1,%2,%3};"
        : "+f"(d[0]), "+f"(d[1]), "+f"(d[2]), "+f"(d[3])
        : "r"(a[0]), "r"(a[1]), "r"(a[2]), "r"(a[3]), "r"(b[0]), "r"(b[1]));
}

// ---------------- prep ----------------
__global__ void prep_kernel(const float* __restrict__ W_ih, const float* __restrict__ W_hh,
                            const float* __restrict__ b_ih, const float* __restrict__ b_hh,
                            const float* __restrict__ Wp2) {
    int i = blockIdx.x * 256 + threadIdx.x;   // up to 262144
    if (i == 0) g_fixctr = 0;
    {
        uint32_t h, l;
        split_tf32(W_ih[i], h, l);
        g_WihHi[i] = __uint_as_float(h);
        g_WihLo[i] = __uint_as_float(l);
    }
    if (i < 1024) g_bih[i] = b_ih[i] + b_hh[i];
    if (i < 65536) {
        int kk = i >> 8, k = i & 255;
        float wi = W_hh[(0 + k) * 256 + kk];
        float wf = W_hh[(256 + k) * 256 + kk];
        float wg = W_hh[(512 + k) * 256 + kk];
        float wo = W_hh[(768 + k) * 256 + kk];
        __nv_bfloat162 bif = __floats2bfloat162_rn(wi, wf);
        __nv_bfloat162 bgo = __floats2bfloat162_rn(wg, wo);
        unsigned uif = *(unsigned*)&bif;
        unsigned ugo = *(unsigned*)&bgo;
        int kk2 = kk >> 1, half = kk & 1;
        ((uint2*)g_WpackH)[(kk2 << 9) + (k << 1) + half] = make_uint2(uif, ugo);
    }
    if (i < 16384) {
        int j = i >> 5, a = i & 31;
        g_Wp2T[i] = Wp2[a * 512 + j];
    }
}

// ---------------- compose policy head ----------------
__global__ void __launch_bounds__(256) compose_p(
    const float* __restrict__ Wp1, const float* __restrict__ bp1,
    const float* __restrict__ W_feat, const float* __restrict__ b_feat,
    const float* __restrict__ W_emb, const float* __restrict__ b_emb) {
    __shared__ float wrow[1024];
    __shared__ float bred[256];
    int j = blockIdx.x, c = threadIdx.x;
    for (int k = c; k < 1024; k += 256) wrow[k] = Wp1[j * 1024 + k];
    __syncthreads();
    float acc = 0.f;
    for (int k = 0; k < 768; k++) acc = fmaf(wrow[k], W_feat[k * 256 + c], acc);
    for (int k = 0; k < 256; k++) acc = fmaf(wrow[768 + k], W_emb[k * 256 + c], acc);
    uint32_t h, l;
    split_tf32(acc, h, l);
    g_WpeHi[j * 256 + c] = __uint_as_float(h);
    g_WpeLo[j * 256 + c] = __uint_as_float(l);
    float bp = 0.f;
#pragma unroll
    for (int q = 0; q < 4; q++) {
        int k = c + q * 256;
        float bk = (k < 768) ? b_feat[k] : b_emb[k - 768];
        bp = fmaf(wrow[k], bk, bp);
    }
    bred[c] = bp;
    __syncthreads();
    for (int st = 128; st; st >>= 1) {
        if (c < st) bred[c] += bred[c + st];
        __syncthreads();
    }
    if (c == 0) g_bpe[j] = bp1[j] + bred[0];
}

// ---------------- compose value head ----------------
__global__ void __launch_bounds__(256) compose_v(
    const float* __restrict__ Wv1, const float* __restrict__ bv1,
    const float* __restrict__ W_feat, const float* __restrict__ b_feat) {
    __shared__ float wrow[768];
    __shared__ float bred[256];
    int j = blockIdx.x, c = threadIdx.x;
    for (int k = c; k < 768; k += 256) wrow[k] = Wv1[j * 1024 + k];
    __syncthreads();
    float acc = 0.f;
    for (int k = 0; k < 768; k++) acc = fmaf(wrow[k], W_feat[k * 256 + c], acc);
    uint32_t h, l;
    split_tf32(acc, h, l);
    g_WveHi[j * 512 + c] = __uint_as_float(h);
    g_WveLo[j * 512 + c] = __uint_as_float(l);
    split_tf32(Wv1[j * 1024 + 768 + c], h, l);
    g_WveHi[j * 512 + 256 + c] = __uint_as_float(h);
    g_WveLo[j * 512 + 256 + c] = __uint_as_float(l);
    float bp = 0.f;
#pragma unroll
    for (int q = 0; q < 3; q++) {
        int k = c + q * 256;
        bp = fmaf(wrow[k], b_feat[k], bp);
    }
    bred[c] = bp;
    __syncthreads();
    for (int st = 128; st; st >>= 1) {
        if (c < st) bred[c] += bred[c + st];
        __syncthreads();
    }
    if (c == 0) g_bve[j] = bv1[j] + bred[0];
}

// ---------------- h_pi/c_pi masked passthrough ----------------
__global__ void hpi_kernel(const float* __restrict__ starts, const float* __restrict__ h_pi,
                           const float* __restrict__ c_pi, float* __restrict__ out) {
    int s = blockIdx.x, tid = threadIdx.x;
    __shared__ float red[256];
    float p = 1.f;
    for (int t = tid; t < TSTEPS; t += 256) p *= (1.f - starts[s * TSTEPS + t]);
    red[tid] = p;
    __syncthreads();
    for (int st = 128; st; st >>= 1) {
        if (tid < st) red[tid] *= red[tid + st];
        __syncthreads();
    }
    float m = red[0];
    size_t base = (size_t)3 * NROWS;
    out[base + s * 256 + tid] = h_pi[s * 256 + tid] * m;
    out[base + 16384 + s * 256 + tid] = c_pi[s * 256 + tid] * m;
}

// ---------------- mma.sync tf32 2-term GEMM ----------------
// acc = Ahi*Bhi + Ahi*Blo  (A-lo dropped; err ~2^-11 rel, argmax covered by fixup)
// MODE 0: cols -> xg LSTM layout.  MODE 1: relu -> C0[n*512+c].
#define PADK 20

template <int MODE>
__global__ void __launch_bounds__(256, 2) mma_gemm(
    const float* __restrict__ A0, const float* __restrict__ A1,
    int K0, int Ktot, int lda0, int lda1,
    const float* __restrict__ WHi, const float* __restrict__ WLo, int ldw,
    const float* __restrict__ bias,
    float* __restrict__ C0, float* __restrict__ C2) {
    __shared__ __align__(16) float smem[3 * 128 * PADK];  // 30720 B
    float* sAh = smem;
    float* sBh = smem + 128 * PADK;
    float* sBl = smem + 2 * 128 * PADK;

    int tid = threadIdx.x, lane = tid & 31, wid = tid >> 5;
    int wr = wid >> 2, wc = wid & 3;
    int rowBase = blockIdx.y * 128, colBase = blockIdx.x * 128;

    float acc[4][4][4];
#pragma unroll
    for (int a = 0; a < 4; a++)
#pragma unroll
        for (int b = 0; b < 4; b++)
#pragma unroll
            for (int c = 0; c < 4; c++) acc[a][b][c] = 0.f;

    int rowL = tid >> 1, colL = (tid & 1) * 8;
    const int nK = Ktot / 16;

    for (int kt = 0; kt < nK; kt++) {
        int kb = kt * 16;
        const float* Asrc;
        int lda, kloc;
        if (kb < K0) { Asrc = A0; lda = lda0; kloc = kb; }
        else { Asrc = A1; lda = lda1; kloc = kb - K0; }
        const float* ap = Asrc + (size_t)(rowBase + rowL) * lda + kloc + colL;
        const float* bhp = WHi + (size_t)(colBase + rowL) * ldw + kb + colL;
        const float* blp = WLo + (size_t)(colBase + rowL) * ldw + kb + colL;
#pragma unroll
        for (int q = 0; q < 2; q++) {
            float4 v = *(const float4*)(ap + q * 4);
            int off = rowL * PADK + colL + q * 4;
            *(uint4*)&sAh[off] = make_uint4(tf32r(v.x), tf32r(v.y), tf32r(v.z), tf32r(v.w));
        }
#pragma unroll
        for (int q = 0; q < 2; q++) {
            int off = rowL * PADK + colL + q * 4;
            *(float4*)&sBh[off] = *(const float4*)(bhp + q * 4);
            *(float4*)&sBl[off] = *(const float4*)(blp + q * 4);
        }
        __syncthreads();

#pragma unroll
        for (int ks = 0; ks < 2; ks++) {
            int kcol = ks * 8 + (lane & 3);
            uint32_t bh4[4][2], bl4[4][2];
#pragma unroll
            for (int ni = 0; ni < 4; ni++) {
                int nrow = wc * 32 + ni * 8 + (lane >> 2);
                bh4[ni][0] = __float_as_uint(sBh[nrow * PADK + kcol]);
                bh4[ni][1] = __float_as_uint(sBh[nrow * PADK + kcol + 4]);
                bl4[ni][0] = __float_as_uint(sBl[nrow * PADK + kcol]);
                bl4[ni][1] = __float_as_uint(sBl[nrow * PADK + kcol + 4]);
            }
#pragma unroll
            for (int mi = 0; mi < 4; mi++) {
                int mrow = wr * 64 + mi * 16 + (lane >> 2);
                uint32_t ah[4];
                ah[0] = __float_as_uint(sAh[mrow * PADK + kcol]);
                ah[1] = __float_as_uint(sAh[(mrow + 8) * PADK + kcol]);
                ah[2] = __float_as_uint(sAh[mrow * PADK + kcol + 4]);
                ah[3] = __float_as_uint(sAh[(mrow + 8) * PADK + kcol + 4]);
#pragma unroll
                for (int ni = 0; ni < 4; ni++) {
                    mma_tf32(acc[mi][ni], ah, bl4[ni]);
                    mma_tf32(acc[mi][ni], ah, bh4[ni]);
                }
            }
        }
        __syncthreads();
    }

    // ---- epilogue: 4 phases of 32 rows staged through smem ----
    float* T = smem;   // 32 x 132 floats = 16896 B <= 30720
#pragma unroll
    for (int p = 0; p < 4; p++) {
        if (wr == (p >> 1)) {
            int miBase = (p & 1) * 2;
#pragma unroll
            for (int mo = 0; mo < 2; mo++) {
                int mi = miBase + mo;
#pragma unroll
                for (int ni = 0; ni < 4; ni++) {
                    int rp = mo * 16 + (lane >> 2);
                    int cc = wc * 32 + ni * 8 + (lane & 3) * 2;
                    *(float2*)&T[rp * 132 + cc] = make_float2(acc[mi][ni][0], acc[mi][ni][1]);
                    *(float2*)&T[(rp + 8) * 132 + cc] = make_float2(acc[mi][ni][2], acc[mi][ni][3]);
                }
            }
        }
        __syncthreads();
#pragma unroll
        for (int i = 0; i < 4; i++) {
            int lin = tid + i * 256;
            int rr = lin >> 5, c4 = (lin & 31) * 4;
            float4 v = *(float4*)&T[rr * 132 + c4];
            float4 bv = *(const float4*)&bias[colBase + c4];
            v.x += bv.x; v.y += bv.y; v.z += bv.z; v.w += bv.w;
            int n = rowBase + p * 32 + rr;
            int c = colBase + c4;
            if (MODE == 1) {
                v.x = fmaxf(v.x, 0.f); v.y = fmaxf(v.y, 0.f); v.z = fmaxf(v.z, 0.f); v.w = fmaxf(v.w, 0.f);
                *(float4*)&C0[((size_t)n << 9) + c] = v;
            } else {
                int sq = n >> 11, tt = n & 2047;
                *(float4*)&C2[((size_t)((tt << 6) | sq) << 10) + c] = v;
            }
        }
        __syncthreads();
    }
}

// ---------------- LSTM scan: one CTA per sequence, 1024 threads, 4-way k-split, xg prefetch ----------------
__global__ void __launch_bounds__(1024) lstm_kernel(
    const float* __restrict__ starts, const float* __restrict__ h0,
    const float* __restrict__ c0v, const uint4* __restrict__ WpH,
    const float* __restrict__ xg, float* __restrict__ hs,
    float* __restrict__ out) {
    int s = blockIdx.x;
    int tid = threadIdx.x;
    int k = tid & 255;
    int j = tid >> 8;
    __shared__ __align__(16) float2 hbuf[256];
    __shared__ __align__(16) float4 psum[4][256];

    float c = 0.f, hn = 0.f;
    float4 xr = make_float4(0.f, 0.f, 0.f, 0.f);
    float str = 0.f;
    if (j == 0) {
        c = c0v[s * 256 + k];
        float h = h0[s * 256 + k];
        hbuf[k] = make_float2(h, h);
        const float* xp = xg + ((size_t)s << 10);
        xr.x = xp[k]; xr.y = xp[256 + k]; xr.z = xp[512 + k]; xr.w = xp[768 + k];
        str = starts[s * TSTEPS];
    }
    __syncthreads();

    const uint4* __restrict__ wbase = WpH + (j << 13);
    const ulonglong2* hb2 = (const ulonglong2*)hbuf;

    for (int t = 0; t < TSTEPS; t++) {
        unsigned long long aif = 0ULL, ago = 0ULL;
#pragma unroll 8
        for (int q = 0; q < 32; q++) {
            uint4 w = wbase[(q << 8) + k];
            ulonglong2 hh = hb2[(j << 5) + q];
            aif = ffma2(bfexp(w.x), hh.x, aif);
            ago = ffma2(bfexp(w.y), hh.x, ago);
            aif = ffma2(bfexp(w.z), hh.y, aif);
            ago = ffma2(bfexp(w.w), hh.y, ago);
        }
        float p0, p1, p2, p3;
        unpack2(aif, p0, p1);
        unpack2(ago, p2, p3);
        psum[j][k] = make_float4(p0, p1, p2, p3);
        __syncthreads();
        if (j == 0) {
            float4 q1 = psum[1][k];
            float4 q2 = psum[2][k];
            float4 q3 = psum[3][k];
            float m = 1.0f - str;
            float xi = xr.x, xf = xr.y, xgg = xr.z, xo = xr.w;
            if (t + 1 < TSTEPS) {
                const float* xp = xg + ((size_t)((t + 1) * 64 + s) << 10);
                xr.x = xp[k]; xr.y = xp[256 + k]; xr.z = xp[512 + k]; xr.w = xp[768 + k];
                str = starts[s * TSTEPS + t + 1];
            }
            float di = p0 + q1.x + q2.x + q3.x;
            float df = p1 + q1.y + q2.y + q3.y;
            float dg = p2 + q1.z + q2.z + q3.z;
            float dq = p3 + q1.w + q2.w + q3.w;
            float gi = xi + m * di;
            float gf = xf + m * df;
            float gg = xgg + m * dg;
            float go = xo + m * dq;
            c *= m;
            c = sigf(gf) * c + sigf(gi) * tanha(gg);
            hn = sigf(go) * tanha(c);
            hs[((size_t)s * TSTEPS + t) * 256 + k] = hn;
            hbuf[k] = make_float2(hn, hn);
        }
        __syncthreads();
    }
    if (j == 0) {
        size_t base = (size_t)3 * NROWS;
        out[base + 32768 + s * 256 + k] = hn;
        out[base + 49152 + s * 256 + k] = c;
    }
}

// ---------------- final: logits, argmax, log_prob, value, near-tie flag ----------------
__global__ void __launch_bounds__(256) head_final(
    const float* __restrict__ HP, const float* __restrict__ HV,
    const float* __restrict__ bp2, const float* __restrict__ Wv2,
    const float* __restrict__ bv2, const float* __restrict__ Wp2T,
    float* __restrict__ out) {
    extern __shared__ float sm[];
    float* sW = sm;            // 16384
    float* sRow = sm + 16384;  // 8*512
    int tid = threadIdx.x, lane = tid & 31, w = tid >> 5;
    for (int i = tid; i < 16384; i += 256) sW[i] = Wp2T[i];
    __syncthreads();
    int n = blockIdx.x * 8 + w;

#pragma unroll
    for (int i = 0; i < 16; i++) sRow[w * 512 + i * 32 + lane] = HP[((size_t)n << 9) + i * 32 + lane];
    __syncwarp();

    float acc = bp2[lane];
    const float* r = &sRow[w * 512];
#pragma unroll 8
    for (int j = 0; j < 512; j++) acc = fmaf(sW[j * 32 + lane], r[j], acc);

    float vacc = 0.f;
#pragma unroll
    for (int i = 0; i < 16; i++) vacc = fmaf(Wv2[i * 32 + lane], HV[((size_t)n << 9) + i * 32 + lane], vacc);
#pragma unroll
    for (int o = 16; o; o >>= 1) vacc += __shfl_xor_sync(0xffffffffu, vacc, o);

    float l = acc;
    float mx = l;
#pragma unroll
    for (int o = 16; o; o >>= 1) mx = fmaxf(mx, __shfl_xor_sync(0xffffffffu, mx, o));
    int best = (l == mx) ? lane : 64;
#pragma unroll
    for (int o = 16; o; o >>= 1) best = min(best, __shfl_xor_sync(0xffffffffu, best, o));
    float e = expf(l - mx);
#pragma unroll
    for (int o = 16; o; o >>= 1) e += __shfl_xor_sync(0xffffffffu, e, o);

    float lnb = (lane == best) ? -1e30f : l;
#pragma unroll
    for (int o = 16; o; o >>= 1) lnb = fmaxf(lnb, __shfl_xor_sync(0xffffffffu, lnb, o));

    if (lane == 0) {
        out[n] = (float)best;
        out[NROWS + n] = vacc + bv2[0];
        out[2 * NROWS + n] = -logf(e);
        if (mx - lnb < 6e-4f) {
            int id = atomicAdd(&g_fixctr, 1);
            if (id < 65536) g_fixlist[id] = n;
        }
    }
}

// ---------------- fixup: exact fp32 policy chain, 8 rows per batch ----------------
#define FB 8
__global__ void __launch_bounds__(256) fixup_kernel(
    const float* __restrict__ features,
    const float* __restrict__ W_feat, const float* __restrict__ b_feat,
    const float* __restrict__ W_emb, const float* __restrict__ b_emb,
    const float* __restrict__ Wp1, const float* __restrict__ bp1,
    const float* __restrict__ Wp2, const float* __restrict__ bp2,
    float* __restrict__ out) {
    extern __shared__ float fsm[];
    float* sx = fsm;                 // FB*256 = 2048
    float* lat = fsm + 2048;         // 1024*FB = 8192
    float* hp = fsm + 2048 + 8192;   // 512*FB = 4096
    float* lg = fsm + 2048 + 8192 + 4096;  // 32*FB = 256
    __shared__ int rows[FB];
    int tid = threadIdx.x, lane = tid & 31, w = tid >> 5;
    int cnt = g_fixctr;
    if (cnt > 65536) cnt = 65536;
    for (int base = blockIdx.x * FB; base < cnt; base += gridDim.x * FB) {
        int nb = min(FB, cnt - base);
        if (tid < FB) rows[tid] = g_fixlist[base + min(tid, nb - 1)];
        __syncthreads();
#pragma unroll
        for (int r = 0; r < FB; r++) sx[r * 256 + tid] = features[(size_t)rows[r] * 256 + tid];
        __syncthreads();
#pragma unroll
        for (int q = 0; q < 4; q++) {
            int jj = tid + q * 256;
            const float* wr;
            float bb;
            if (jj < 768) { wr = W_feat + (size_t)jj * 256; bb = b_feat[jj]; }
            else { wr = W_emb + (size_t)(jj - 768) * 256; bb = b_emb[jj - 768]; }
            float a[FB];
#pragma unroll
            for (int r = 0; r < FB; r++) a[r] = bb;
            for (int kk = 0; kk < 256; kk++) {
                float wv = wr[kk];
#pragma unroll
                for (int r = 0; r < FB; r++) a[r] = fmaf(wv, sx[r * 256 + kk], a[r]);
            }
#pragma unroll
            for (int r = 0; r < FB; r++) lat[jj * FB + r] = a[r];
        }
        __syncthreads();
#pragma unroll
        for (int q = 0; q < 2; q++) {
            int jj = tid + q * 256;
            const float* wr = Wp1 + (size_t)jj * 1024;
            float a[FB];
            float bb = bp1[jj];
#pragma unroll
            for (int r = 0; r < FB; r++) a[r] = bb;
            for (int kk = 0; kk < 1024; kk++) {
                float wv = wr[kk];
#pragma unroll
                for (int r = 0; r < FB; r++) a[r] = fmaf(wv, lat[kk * FB + r], a[r]);
            }
#pragma unroll
            for (int r = 0; r < FB; r++) hp[jj * FB + r] = fmaxf(a[r], 0.f);
        }
        __syncthreads();
        {
            int ai = tid >> 3, r = tid & 7;
            const float* wr = Wp2 + (size_t)ai * 512;
            float p = bp2[ai];
            for (int kk = 0; kk < 512; kk++) p = fmaf(wr[kk], hp[kk * FB + r], p);
            lg[ai * FB + r] = p;
        }
        __syncthreads();
        if (w < nb) {
            float l = lg[lane * FB + w];
            float mx = l;
#pragma unroll
            for (int o = 16; o; o >>= 1) mx = fmaxf(mx, __shfl_xor_sync(0xffffffffu, mx, o));
            int best = (l == mx) ? lane : 64;
#pragma unroll
            for (int o = 16; o; o >>= 1) best = min(best, __shfl_xor_sync(0xffffffffu, best, o));
            float e = expf(l - mx);
#pragma unroll
            for (int o = 16; o; o >>= 1) e += __shfl_xor_sync(0xffffffffu, e, o);
            if (lane == 0) {
                int n = rows[w];
                out[n] = (float)best;
                out[2 * NROWS + n] = -logf(e);
            }
        }
        __syncthreads();
    }
}

// ---------------- launch ----------------
extern "C" void kernel_launch(void* const* d_in, const int* in_sizes, int n_in,
                              void* d_out, int out_size) {
    const float* features = (const float*)d_in[0];
    const float* episode_starts = (const float*)d_in[1];
    const float* h_pi = (const float*)d_in[2];
    const float* c_pi = (const float*)d_in[3];
    const float* h_vf = (const float*)d_in[4];
    const float* c_vf = (const float*)d_in[5];
    const float* W_feat = (const float*)d_in[6];
    const float* b_feat = (const float*)d_in[7];
    const float* W_emb = (const float*)d_in[8];
    const float* b_emb = (const float*)d_in[9];
    const float* W_ih = (const float*)d_in[10];
    const float* W_hh = (const float*)d_in[11];
    const float* b_ih = (const float*)d_in[12];
    const float* b_hh = (const float*)d_in[13];
    const float* Wp1 = (const float*)d_in[14];
    const float* bp1 = (const float*)d_in[15];
    const float* Wp2 = (const float*)d_in[16];
    const float* bp2 = (const float*)d_in[17];
    const float* Wv1 = (const float*)d_in[18];
    const float* bv1 = (const float*)d_in[19];
    const float* Wv2 = (const float*)d_in[20];
    const float* bv2 = (const float*)d_in[21];
    float* out = (float*)d_out;

    float *p_WihHi, *p_WihLo, *p_bih, *p_Wp2T, *p_xg, *p_hs;
    float *p_WpeHi, *p_WpeLo, *p_bpe, *p_WveHi, *p_WveLo, *p_bve;
    uint4* p_WpH;
    cudaGetSymbolAddress((void**)&p_WihHi, g_WihHi);
    cudaGetSymbolAddress((void**)&p_WihLo, g_WihLo);
    cudaGetSymbolAddress((void**)&p_bih, g_bih);
    cudaGetSymbolAddress((void**)&p_WpH, g_WpackH);
    cudaGetSymbolAddress((void**)&p_Wp2T, g_Wp2T);
    cudaGetSymbolAddress((void**)&p_WpeHi, g_WpeHi);
    cudaGetSymbolAddress((void**)&p_WpeLo, g_WpeLo);
    cudaGetSymbolAddress((void**)&p_bpe, g_bpe);
    cudaGetSymbolAddress((void**)&p_WveHi, g_WveHi);
    cudaGetSymbolAddress((void**)&p_WveLo, g_WveLo);
    cudaGetSymbolAddress((void**)&p_bve, g_bve);
    cudaGetSymbolAddress((void**)&p_xg, g_xg);
    cudaGetSymbolAddress((void**)&p_hs, g_hs);
    float* p_HP = p_xg;
    float* p_HV = p_xg + (size_t)NROWS * 512;

    cudaFuncSetAttribute(head_final, cudaFuncAttributeMaxDynamicSharedMemorySize, 81920);
    cudaFuncSetAttribute(fixup_kernel, cudaFuncAttributeMaxDynamicSharedMemorySize, 60000);

    prep_kernel<<<1024, 256>>>(W_ih, W_hh, b_ih, b_hh, Wp2);
    compose_p<<<512, 256>>>(Wp1, bp1, W_feat, b_feat, W_emb, b_emb);
    compose_v<<<512, 256>>>(Wv1, bv1, W_feat, b_feat);
    hpi_kernel<<<NSEQ, 256>>>(episode_starts, h_pi, c_pi, out);

    // xg GEMM -> LSTM (sequential; LSTM must own all L2 bandwidth)
    mma_gemm<0><<<dim3(1024 / 128, NROWS / 128), 256>>>(
        features, features, 256, 256, 256, 256, p_WihHi, p_WihLo, 256, p_bih, nullptr, p_xg);

    lstm_kernel<<<NSEQ, 1024>>>(episode_starts, h_vf, c_vf, p_WpH, p_xg, p_hs, out);

    // policy head: feats(256) @ Weff_p^T -> relu -> HP (aliases xg, consumed already)
    mma_gemm<1><<<dim3(512 / 128, NROWS / 128), 256>>>(
        features, features, 256, 256, 256, 256, p_WpeHi, p_WpeLo, 256, p_bpe, p_HP, nullptr);
    // value head: [feats(256), hs(256)] @ Wve^T -> relu -> HV
    mma_gemm<1><<<dim3(512 / 128, NROWS / 128), 256>>>(
        features, p_hs, 256, 512, 256, 256, p_WveHi, p_WveLo, 512, p_bve, p_HV, nullptr);

    head_final<<<NROWS / 8, 256, 81920>>>(p_HP, p_HV, bp2, Wv2, bv2, p_Wp2T, out);
    fixup_kernel<<<256, 256, 60000>>>(features, W_feat, b_feat, W_emb, b_emb, Wp1, bp1, Wp2, bp2, out);
}

// round 14
// speedup vs baseline: 1.8171x; 1.8171x over previous
#include <cuda_runtime.h>
#include <cuda_bf16.h>
#include <cstdint>
#include <cstddef>

#define NROWS 131072
#define NSEQ 64
#define TSTEPS 2048

// ---------------- scratch ----------------
__device__ __align__(16) float g_WihHi[1024 * 256];
__device__ __align__(16) float g_WihLo[1024 * 256];
__device__ float g_bih[1024];
__device__ __align__(16) uint4 g_WpackH[128 * 256];
__device__ float g_Wp2T[512 * 32];
__device__ __align__(16) float g_WpeHi[512 * 256];
__device__ __align__(16) float g_WpeLo[512 * 256];
__device__ float g_bpe[512];
__device__ __align__(16) float g_WveHi[512 * 512];
__device__ __align__(16) float g_WveLo[512 * 512];
__device__ float g_bve[512];
__device__ __align__(16) float g_xg[(size_t)NROWS * 1024];   // xg; reused as HP/HV after LSTM
__device__ __align__(16) float g_hs[(size_t)NROWS * 256];
__device__ int g_fixctr;
__device__ int g_fixlist[65536];

// ---------------- helpers ----------------
__device__ __forceinline__ unsigned long long ffma2(unsigned long long a, unsigned long long b, unsigned long long c) {
    asm("fma.rn.f32x2 %0, %1, %2, %3;" : "=l"(c) : "l"(a), "l"(b), "l"(c));
    return c;
}
__device__ __forceinline__ void unpack2(unsigned long long v, float& a, float& b) {
    asm("mov.b64 {%0, %1}, %2;" : "=f"(a), "=f"(b) : "l"(v));
}
__device__ __forceinline__ unsigned long long pack2b(unsigned lo, unsigned hi) {
    unsigned long long r;
    asm("mov.b64 %0, {%1, %2};" : "=l"(r) : "r"(lo), "r"(hi));
    return r;
}
__device__ __forceinline__ unsigned long long bfexp(unsigned r) {
    return pack2b(r << 16, r & 0xffff0000u);
}
__device__ __forceinline__ float sigf(float x) { return __fdividef(1.f, 1.f + __expf(-x)); }
__device__ __forceinline__ float tanha(float x) {
    float y;
    asm("tanh.approx.f32 %0, %1;" : "=f"(y) : "f"(x));
    return y;
}
__device__ __forceinline__ void split_tf32(float x, uint32_t& h, uint32_t& l) {
    asm("cvt.rna.tf32.f32 %0, %1;" : "=r"(h) : "f"(x));
    float lo = x - __uint_as_float(h);
    asm("cvt.rna.tf32.f32 %0, %1;" : "=r"(l) : "f"(lo));
}
__device__ __forceinline__ uint32_t tf32r(float x) {
    uint32_t h;
    asm("cvt.rna.tf32.f32 %0, %1;" : "=r"(h) : "f"(x));
    return h;
}
__device__ __forceinline__ void mma_tf32(float* d, const uint32_t* a, const uint32_t* b) {
    asm volatile(
        "mma.sync.aligned.m16n8k8.row.col.f32.tf32.tf32.f32 "
        "{%0,%1,%2,%3}, {%4,%5,%6,%7}, {%8,%9}, {%0,%1,%2,%3};"
        : "+f"(d[0]), "+f"(d[1]), "+f"(d[2]), "+f"(d[3])
        : "r"(a[0]), "r"(a[1]), "r"(a[2]), "r"(a[3]), "r"(b[0]), "r"(b[1]));
}

// ---------------- prep ----------------
__global__ void prep_kernel(const float* __restrict__ W_ih, const float* __restrict__ W_hh,
                            const float* __restrict__ b_ih, const float* __restrict__ b_hh,
                            const float* __restrict__ Wp2) {
    int i = blockIdx.x * 256 + threadIdx.x;   // up to 262144
    if (i == 0) g_fixctr = 0;
    {
        uint32_t h, l;
        split_tf32(W_ih[i], h, l);
        g_WihHi[i] = __uint_as_float(h);
        g_WihLo[i] = __uint_as_float(l);
    }
    if (i < 1024) g_bih[i] = b_ih[i] + b_hh[i];
    if (i < 65536) {
        int kk = i >> 8, k = i & 255;
        float wi = W_hh[(0 + k) * 256 + kk];
        float wf = W_hh[(256 + k) * 256 + kk];
        float wg = W_hh[(512 + k) * 256 + kk];
        float wo = W_hh[(768 + k) * 256 + kk];
        __nv_bfloat162 bif = __floats2bfloat162_rn(wi, wf);
        __nv_bfloat162 bgo = __floats2bfloat162_rn(wg, wo);
        unsigned uif = *(unsigned*)&bif;
        unsigned ugo = *(unsigned*)&bgo;
        int kk2 = kk >> 1, half = kk & 1;
        ((uint2*)g_WpackH)[(kk2 << 9) + (k << 1) + half] = make_uint2(uif, ugo);
    }
    if (i < 16384) {
        int j = i >> 5, a = i & 31;
        g_Wp2T[i] = Wp2[a * 512 + j];
    }
}

// ---------------- compose policy head ----------------
__global__ void __launch_bounds__(256) compose_p(
    const float* __restrict__ Wp1, const float* __restrict__ bp1,
    const float* __restrict__ W_feat, const float* __restrict__ b_feat,
    const float* __restrict__ W_emb, const float* __restrict__ b_emb) {
    __shared__ float wrow[1024];
    __shared__ float bred[256];
    int j = blockIdx.x, c = threadIdx.x;
    for (int k = c; k < 1024; k += 256) wrow[k] = Wp1[j * 1024 + k];
    __syncthreads();
    float acc = 0.f;
    for (int k = 0; k < 768; k++) acc = fmaf(wrow[k], W_feat[k * 256 + c], acc);
    for (int k = 0; k < 256; k++) acc = fmaf(wrow[768 + k], W_emb[k * 256 + c], acc);
    uint32_t h, l;
    split_tf32(acc, h, l);
    g_WpeHi[j * 256 + c] = __uint_as_float(h);
    g_WpeLo[j * 256 + c] = __uint_as_float(l);
    float bp = 0.f;
#pragma unroll
    for (int q = 0; q < 4; q++) {
        int k = c + q * 256;
        float bk = (k < 768) ? b_feat[k] : b_emb[k - 768];
        bp = fmaf(wrow[k], bk, bp);
    }
    bred[c] = bp;
    __syncthreads();
    for (int st = 128; st; st >>= 1) {
        if (c < st) bred[c] += bred[c + st];
        __syncthreads();
    }
    if (c == 0) g_bpe[j] = bp1[j] + bred[0];
}

// ---------------- compose value head ----------------
__global__ void __launch_bounds__(256) compose_v(
    const float* __restrict__ Wv1, const float* __restrict__ bv1,
    const float* __restrict__ W_feat, const float* __restrict__ b_feat) {
    __shared__ float wrow[768];
    __shared__ float bred[256];
    int j = blockIdx.x, c = threadIdx.x;
    for (int k = c; k < 768; k += 256) wrow[k] = Wv1[j * 1024 + k];
    __syncthreads();
    float acc = 0.f;
    for (int k = 0; k < 768; k++) acc = fmaf(wrow[k], W_feat[k * 256 + c], acc);
    uint32_t h, l;
    split_tf32(acc, h, l);
    g_WveHi[j * 512 + c] = __uint_as_float(h);
    g_WveLo[j * 512 + c] = __uint_as_float(l);
    split_tf32(Wv1[j * 1024 + 768 + c], h, l);
    g_WveHi[j * 512 + 256 + c] = __uint_as_float(h);
    g_WveLo[j * 512 + 256 + c] = __uint_as_float(l);
    float bp = 0.f;
#pragma unroll
    for (int q = 0; q < 3; q++) {
        int k = c + q * 256;
        bp = fmaf(wrow[k], b_feat[k], bp);
    }
    bred[c] = bp;
    __syncthreads();
    for (int st = 128; st; st >>= 1) {
        if (c < st) bred[c] += bred[c + st];
        __syncthreads();
    }
    if (c == 0) g_bve[j] = bv1[j] + bred[0];
}

// ---------------- h_pi/c_pi masked passthrough ----------------
__global__ void hpi_kernel(const float* __restrict__ starts, const float* __restrict__ h_pi,
                           const float* __restrict__ c_pi, float* __restrict__ out) {
    int s = blockIdx.x, tid = threadIdx.x;
    __shared__ float red[256];
    float p = 1.f;
    for (int t = tid; t < TSTEPS; t += 256) p *= (1.f - starts[s * TSTEPS + t]);
    red[tid] = p;
    __syncthreads();
    for (int st = 128; st; st >>= 1) {
        if (tid < st) red[tid] *= red[tid + st];
        __syncthreads();
    }
    float m = red[0];
    size_t base = (size_t)3 * NROWS;
    out[base + s * 256 + tid] = h_pi[s * 256 + tid] * m;
    out[base + 16384 + s * 256 + tid] = c_pi[s * 256 + tid] * m;
}

// ---------------- mma.sync tf32 2-term GEMM ----------------
// acc = Ahi*Bhi + Ahi*Blo  (A-lo dropped; err ~2^-11 rel, argmax covered by fixup)
// MODE 0: cols -> xg LSTM layout.  MODE 1: relu -> C0[n*512+c].
#define PADK 20

template <int MODE>
__global__ void __launch_bounds__(256, 2) mma_gemm(
    const float* __restrict__ A0, const float* __restrict__ A1,
    int K0, int Ktot, int lda0, int lda1,
    const float* __restrict__ WHi, const float* __restrict__ WLo, int ldw,
    const float* __restrict__ bias,
    float* __restrict__ C0, float* __restrict__ C2) {
    __shared__ __align__(16) float smem[3 * 128 * PADK];  // 30720 B
    float* sAh = smem;
    float* sBh = smem + 128 * PADK;
    float* sBl = smem + 2 * 128 * PADK;

    int tid = threadIdx.x, lane = tid & 31, wid = tid >> 5;
    int wr = wid >> 2, wc = wid & 3;
    int rowBase = blockIdx.y * 128, colBase = blockIdx.x * 128;

    float acc[4][4][4];
#pragma unroll
    for (int a = 0; a < 4; a++)
#pragma unroll
        for (int b = 0; b < 4; b++)
#pragma unroll
            for (int c = 0; c < 4; c++) acc[a][b][c] = 0.f;

    int rowL = tid >> 1, colL = (tid & 1) * 8;
    const int nK = Ktot / 16;

    for (int kt = 0; kt < nK; kt++) {
        int kb = kt * 16;
        const float* Asrc;
        int lda, kloc;
        if (kb < K0) { Asrc = A0; lda = lda0; kloc = kb; }
        else { Asrc = A1; lda = lda1; kloc = kb - K0; }
        const float* ap = Asrc + (size_t)(rowBase + rowL) * lda + kloc + colL;
        const float* bhp = WHi + (size_t)(colBase + rowL) * ldw + kb + colL;
        const float* blp = WLo + (size_t)(colBase + rowL) * ldw + kb + colL;
#pragma unroll
        for (int q = 0; q < 2; q++) {
            float4 v = *(const float4*)(ap + q * 4);
            int off = rowL * PADK + colL + q * 4;
            *(uint4*)&sAh[off] = make_uint4(tf32r(v.x), tf32r(v.y), tf32r(v.z), tf32r(v.w));
        }
#pragma unroll
        for (int q = 0; q < 2; q++) {
            int off = rowL * PADK + colL + q * 4;
            *(float4*)&sBh[off] = *(const float4*)(bhp + q * 4);
            *(float4*)&sBl[off] = *(const float4*)(blp + q * 4);
        }
        __syncthreads();

#pragma unroll
        for (int ks = 0; ks < 2; ks++) {
            int kcol = ks * 8 + (lane & 3);
            uint32_t bh4[4][2], bl4[4][2];
#pragma unroll
            for (int ni = 0; ni < 4; ni++) {
                int nrow = wc * 32 + ni * 8 + (lane >> 2);
                bh4[ni][0] = __float_as_uint(sBh[nrow * PADK + kcol]);
                bh4[ni][1] = __float_as_uint(sBh[nrow * PADK + kcol + 4]);
                bl4[ni][0] = __float_as_uint(sBl[nrow * PADK + kcol]);
                bl4[ni][1] = __float_as_uint(sBl[nrow * PADK + kcol + 4]);
            }
#pragma unroll
            for (int mi = 0; mi < 4; mi++) {
                int mrow = wr * 64 + mi * 16 + (lane >> 2);
                uint32_t ah[4];
                ah[0] = __float_as_uint(sAh[mrow * PADK + kcol]);
                ah[1] = __float_as_uint(sAh[(mrow + 8) * PADK + kcol]);
                ah[2] = __float_as_uint(sAh[mrow * PADK + kcol + 4]);
                ah[3] = __float_as_uint(sAh[(mrow + 8) * PADK + kcol + 4]);
#pragma unroll
                for (int ni = 0; ni < 4; ni++) {
                    mma_tf32(acc[mi][ni], ah, bl4[ni]);
                    mma_tf32(acc[mi][ni], ah, bh4[ni]);
                }
            }
        }
        __syncthreads();
    }

    // ---- epilogue: 4 phases of 32 rows staged through smem ----
    float* T = smem;   // 32 x 132 floats = 16896 B <= 30720
#pragma unroll
    for (int p = 0; p < 4; p++) {
        if (wr == (p >> 1)) {
            int miBase = (p & 1) * 2;
#pragma unroll
            for (int mo = 0; mo < 2; mo++) {
                int mi = miBase + mo;
#pragma unroll
                for (int ni = 0; ni < 4; ni++) {
                    int rp = mo * 16 + (lane >> 2);
                    int cc = wc * 32 + ni * 8 + (lane & 3) * 2;
                    *(float2*)&T[rp * 132 + cc] = make_float2(acc[mi][ni][0], acc[mi][ni][1]);
                    *(float2*)&T[(rp + 8) * 132 + cc] = make_float2(acc[mi][ni][2], acc[mi][ni][3]);
                }
            }
        }
        __syncthreads();
#pragma unroll
        for (int i = 0; i < 4; i++) {
            int lin = tid + i * 256;
            int rr = lin >> 5, c4 = (lin & 31) * 4;
            float4 v = *(float4*)&T[rr * 132 + c4];
            float4 bv = *(const float4*)&bias[colBase + c4];
            v.x += bv.x; v.y += bv.y; v.z += bv.z; v.w += bv.w;
            int n = rowBase + p * 32 + rr;
            int c = colBase + c4;
            if (MODE == 1) {
                v.x = fmaxf(v.x, 0.f); v.y = fmaxf(v.y, 0.f); v.z = fmaxf(v.z, 0.f); v.w = fmaxf(v.w, 0.f);
                *(float4*)&C0[((size_t)n << 9) + c] = v;
            } else {
                int sq = n >> 11, tt = n & 2047;
                *(float4*)&C2[((size_t)((tt << 6) | sq) << 10) + c] = v;
            }
        }
        __syncthreads();
    }
}

// ---------------- LSTM scan: one CTA per sequence, 1024 threads, 4-way k-split (R8 exact) ----------------
__global__ void __launch_bounds__(1024) lstm_kernel(
    const float* __restrict__ starts, const float* __restrict__ h0,
    const float* __restrict__ c0v, const uint4* __restrict__ WpH,
    const float* __restrict__ xg, float* __restrict__ hs,
    float* __restrict__ out) {
    int s = blockIdx.x;
    int tid = threadIdx.x;
    int k = tid & 255;
    int j = tid >> 8;            // 0..3  -> kk2 slice [32j, 32j+32)
    __shared__ __align__(16) float2 hbuf[256];
    __shared__ __align__(16) float4 psum[4][256];

    float c = 0.f, hn = 0.f;
    if (j == 0) {
        c = c0v[s * 256 + k];
        float h = h0[s * 256 + k];
        hbuf[k] = make_float2(h, h);
    }
    __syncthreads();

    const uint4* __restrict__ wbase = WpH + (j << 13);   // j*32 kk2 * 256
    const ulonglong2* hb2 = (const ulonglong2*)hbuf;

    for (int t = 0; t < TSTEPS; t++) {
        float m = 1.0f - starts[s * TSTEPS + t];
        unsigned long long aif = 0ULL, ago = 0ULL;
#pragma unroll 8
        for (int q = 0; q < 32; q++) {
            uint4 w = wbase[(q << 8) + k];
            ulonglong2 hh = hb2[(j << 5) + q];
            aif = ffma2(bfexp(w.x), hh.x, aif);
            ago = ffma2(bfexp(w.y), hh.x, ago);
            aif = ffma2(bfexp(w.z), hh.y, aif);
            ago = ffma2(bfexp(w.w), hh.y, ago);
        }
        float p0, p1, p2, p3;
        unpack2(aif, p0, p1);
        unpack2(ago, p2, p3);
        psum[j][k] = make_float4(p0, p1, p2, p3);
        __syncthreads();
        if (j == 0) {
            float4 q1 = psum[1][k];
            float4 q2 = psum[2][k];
            float4 q3 = psum[3][k];
            float di = p0 + q1.x + q2.x + q3.x;
            float df = p1 + q1.y + q2.y + q3.y;
            float dg = p2 + q1.z + q2.z + q3.z;
            float dq = p3 + q1.w + q2.w + q3.w;
            const float* xgp = xg + ((size_t)(t * 64 + s) << 10);
            float gi = xgp[k] + m * di;
            float gf = xgp[256 + k] + m * df;
            float gg = xgp[512 + k] + m * dg;
            float go = xgp[768 + k] + m * dq;
            c *= m;
            c = sigf(gf) * c + sigf(gi) * tanha(gg);
            hn = sigf(go) * tanha(c);
            hs[((size_t)s * TSTEPS + t) * 256 + k] = hn;
            hbuf[k] = make_float2(hn, hn);
        }
        __syncthreads();
    }
    if (j == 0) {
        size_t base = (size_t)3 * NROWS;
        out[base + 32768 + s * 256 + k] = hn;
        out[base + 49152 + s * 256 + k] = c;
    }
}

// ---------------- final: logits, argmax, log_prob, value, near-tie flag ----------------
__global__ void __launch_bounds__(256) head_final(
    const float* __restrict__ HP, const float* __restrict__ HV,
    const float* __restrict__ bp2, const float* __restrict__ Wv2,
    const float* __restrict__ bv2, const float* __restrict__ Wp2T,
    float* __restrict__ out) {
    extern __shared__ float sm[];
    float* sW = sm;            // 16384
    float* sRow = sm + 16384;  // 8*512
    int tid = threadIdx.x, lane = tid & 31, w = tid >> 5;
    for (int i = tid; i < 16384; i += 256) sW[i] = Wp2T[i];
    __syncthreads();
    int n = blockIdx.x * 8 + w;

#pragma unroll
    for (int i = 0; i < 16; i++) sRow[w * 512 + i * 32 + lane] = HP[((size_t)n << 9) + i * 32 + lane];
    __syncwarp();

    float acc = bp2[lane];
    const float* r = &sRow[w * 512];
#pragma unroll 8
    for (int j = 0; j < 512; j++) acc = fmaf(sW[j * 32 + lane], r[j], acc);

    float vacc = 0.f;
#pragma unroll
    for (int i = 0; i < 16; i++) vacc = fmaf(Wv2[i * 32 + lane], HV[((size_t)n << 9) + i * 32 + lane], vacc);
#pragma unroll
    for (int o = 16; o; o >>= 1) vacc += __shfl_xor_sync(0xffffffffu, vacc, o);

    float l = acc;
    float mx = l;
#pragma unroll
    for (int o = 16; o; o >>= 1) mx = fmaxf(mx, __shfl_xor_sync(0xffffffffu, mx, o));
    int best = (l == mx) ? lane : 64;
#pragma unroll
    for (int o = 16; o; o >>= 1) best = min(best, __shfl_xor_sync(0xffffffffu, best, o));
    float e = expf(l - mx);
#pragma unroll
    for (int o = 16; o; o >>= 1) e += __shfl_xor_sync(0xffffffffu, e, o);

    float lnb = (lane == best) ? -1e30f : l;
#pragma unroll
    for (int o = 16; o; o >>= 1) lnb = fmaxf(lnb, __shfl_xor_sync(0xffffffffu, lnb, o));

    if (lane == 0) {
        out[n] = (float)best;
        out[NROWS + n] = vacc + bv2[0];
        out[2 * NROWS + n] = -logf(e);
        if (mx - lnb < 6e-4f) {
            int id = atomicAdd(&g_fixctr, 1);
            if (id < 65536) g_fixlist[id] = n;
        }
    }
}

// ---------------- fixup: exact fp32 policy chain, 8 rows per batch ----------------
#define FB 8
__global__ void __launch_bounds__(256) fixup_kernel(
    const float* __restrict__ features,
    const float* __restrict__ W_feat, const float* __restrict__ b_feat,
    const float* __restrict__ W_emb, const float* __restrict__ b_emb,
    const float* __restrict__ Wp1, const float* __restrict__ bp1,
    const float* __restrict__ Wp2, const float* __restrict__ bp2,
    float* __restrict__ out) {
    extern __shared__ float fsm[];
    float* sx = fsm;                 // FB*256 = 2048
    float* lat = fsm + 2048;         // 1024*FB = 8192
    float* hp = fsm + 2048 + 8192;   // 512*FB = 4096
    float* lg = fsm + 2048 + 8192 + 4096;  // 32*FB = 256
    __shared__ int rows[FB];
    int tid = threadIdx.x, lane = tid & 31, w = tid >> 5;
    int cnt = g_fixctr;
    if (cnt > 65536) cnt = 65536;
    for (int base = blockIdx.x * FB; base < cnt; base += gridDim.x * FB) {
        int nb = min(FB, cnt - base);
        if (tid < FB) rows[tid] = g_fixlist[base + min(tid, nb - 1)];
        __syncthreads();
#pragma unroll
        for (int r = 0; r < FB; r++) sx[r * 256 + tid] = features[(size_t)rows[r] * 256 + tid];
        __syncthreads();
#pragma unroll
        for (int q = 0; q < 4; q++) {
            int jj = tid + q * 256;
            const float* wr;
            float bb;
            if (jj < 768) { wr = W_feat + (size_t)jj * 256; bb = b_feat[jj]; }
            else { wr = W_emb + (size_t)(jj - 768) * 256; bb = b_emb[jj - 768]; }
            float a[FB];
#pragma unroll
            for (int r = 0; r < FB; r++) a[r] = bb;
            for (int kk = 0; kk < 256; kk++) {
                float wv = wr[kk];
#pragma unroll
                for (int r = 0; r < FB; r++) a[r] = fmaf(wv, sx[r * 256 + kk], a[r]);
            }
#pragma unroll
            for (int r = 0; r < FB; r++) lat[jj * FB + r] = a[r];
        }
        __syncthreads();
#pragma unroll
        for (int q = 0; q < 2; q++) {
            int jj = tid + q * 256;
            const float* wr = Wp1 + (size_t)jj * 1024;
            float a[FB];
            float bb = bp1[jj];
#pragma unroll
            for (int r = 0; r < FB; r++) a[r] = bb;
            for (int kk = 0; kk < 1024; kk++) {
                float wv = wr[kk];
#pragma unroll
                for (int r = 0; r < FB; r++) a[r] = fmaf(wv, lat[kk * FB + r], a[r]);
            }
#pragma unroll
            for (int r = 0; r < FB; r++) hp[jj * FB + r] = fmaxf(a[r], 0.f);
        }
        __syncthreads();
        {
            int ai = tid >> 3, r = tid & 7;
            const float* wr = Wp2 + (size_t)ai * 512;
            float p = bp2[ai];
            for (int kk = 0; kk < 512; kk++) p = fmaf(wr[kk], hp[kk * FB + r], p);
            lg[ai * FB + r] = p;
        }
        __syncthreads();
        if (w < nb) {
            float l = lg[lane * FB + w];
            float mx = l;
#pragma unroll
            for (int o = 16; o; o >>= 1) mx = fmaxf(mx, __shfl_xor_sync(0xffffffffu, mx, o));
            int best = (l == mx) ? lane : 64;
#pragma unroll
            for (int o = 16; o; o >>= 1) best = min(best, __shfl_xor_sync(0xffffffffu, best, o));
            float e = expf(l - mx);
#pragma unroll
            for (int o = 16; o; o >>= 1) e += __shfl_xor_sync(0xffffffffu, e, o);
            if (lane == 0) {
                int n = rows[w];
                out[n] = (float)best;
                out[2 * NROWS + n] = -logf(e);
            }
        }
        __syncthreads();
    }
}

// ---------------- launch ----------------
extern "C" void kernel_launch(void* const* d_in, const int* in_sizes, int n_in,
                              void* d_out, int out_size) {
    const float* features = (const float*)d_in[0];
    const float* episode_starts = (const float*)d_in[1];
    const float* h_pi = (const float*)d_in[2];
    const float* c_pi = (const float*)d_in[3];
    const float* h_vf = (const float*)d_in[4];
    const float* c_vf = (const float*)d_in[5];
    const float* W_feat = (const float*)d_in[6];
    const float* b_feat = (const float*)d_in[7];
    const float* W_emb = (const float*)d_in[8];
    const float* b_emb = (const float*)d_in[9];
    const float* W_ih = (const float*)d_in[10];
    const float* W_hh = (const float*)d_in[11];
    const float* b_ih = (const float*)d_in[12];
    const float* b_hh = (const float*)d_in[13];
    const float* Wp1 = (const float*)d_in[14];
    const float* bp1 = (const float*)d_in[15];
    const float* Wp2 = (const float*)d_in[16];
    const float* bp2 = (const float*)d_in[17];
    const float* Wv1 = (const float*)d_in[18];
    const float* bv1 = (const float*)d_in[19];
    const float* Wv2 = (const float*)d_in[20];
    const float* bv2 = (const float*)d_in[21];
    float* out = (float*)d_out;

    float *p_WihHi, *p_WihLo, *p_bih, *p_Wp2T, *p_xg, *p_hs;
    float *p_WpeHi, *p_WpeLo, *p_bpe, *p_WveHi, *p_WveLo, *p_bve;
    uint4* p_WpH;
    cudaGetSymbolAddress((void**)&p_WihHi, g_WihHi);
    cudaGetSymbolAddress((void**)&p_WihLo, g_WihLo);
    cudaGetSymbolAddress((void**)&p_bih, g_bih);
    cudaGetSymbolAddress((void**)&p_WpH, g_WpackH);
    cudaGetSymbolAddress((void**)&p_Wp2T, g_Wp2T);
    cudaGetSymbolAddress((void**)&p_WpeHi, g_WpeHi);
    cudaGetSymbolAddress((void**)&p_WpeLo, g_WpeLo);
    cudaGetSymbolAddress((void**)&p_bpe, g_bpe);
    cudaGetSymbolAddress((void**)&p_WveHi, g_WveHi);
    cudaGetSymbolAddress((void**)&p_WveLo, g_WveLo);
    cudaGetSymbolAddress((void**)&p_bve, g_bve);
    cudaGetSymbolAddress((void**)&p_xg, g_xg);
    cudaGetSymbolAddress((void**)&p_hs, g_hs);
    float* p_HP = p_xg;
    float* p_HV = p_xg + (size_t)NROWS * 512;

    cudaFuncSetAttribute(head_final, cudaFuncAttributeMaxDynamicSharedMemorySize, 81920);
    cudaFuncSetAttribute(fixup_kernel, cudaFuncAttributeMaxDynamicSharedMemorySize, 60000);

    prep_kernel<<<1024, 256>>>(W_ih, W_hh, b_ih, b_hh, Wp2);
    compose_p<<<512, 256>>>(Wp1, bp1, W_feat, b_feat, W_emb, b_emb);
    compose_v<<<512, 256>>>(Wv1, bv1, W_feat, b_feat);
    hpi_kernel<<<NSEQ, 256>>>(episode_starts, h_pi, c_pi, out);

    // xg GEMM -> LSTM (sequential; LSTM owns all L2 bandwidth)
    mma_gemm<0><<<dim3(1024 / 128, NROWS / 128), 256>>>(
        features, features, 256, 256, 256, 256, p_WihHi, p_WihLo, 256, p_bih, nullptr, p_xg);

    lstm_kernel<<<NSEQ, 1024>>>(episode_starts, h_vf, c_vf, p_WpH, p_xg, p_hs, out);

    // policy head: feats(256) @ Weff_p^T -> relu -> HP (aliases xg, consumed already)
    mma_gemm<1><<<dim3(512 / 128, NROWS / 128), 256>>>(
        features, features, 256, 256, 256, 256, p_WpeHi, p_WpeLo, 256, p_bpe, p_HP, nullptr);
    // value head: [feats(256), hs(256)] @ Wve^T -> relu -> HV
    mma_gemm<1><<<dim3(512 / 128, NROWS / 128), 256>>>(
        features, p_hs, 256, 512, 256, 256, p_WveHi, p_WveLo, 512, p_bve, p_HV, nullptr);

    head_final<<<NROWS / 8, 256, 81920>>>(p_HP, p_HV, bp2, Wv2, bv2, p_Wp2T, out);
    fixup_kernel<<<256, 256, 60000>>>(features, W_feat, b_feat, W_emb, b_emb, Wp1, bp1, Wp2, bp2, out);
}